// round 6
// baseline (speedup 1.0000x reference)
#include <cuda_runtime.h>
#include <cuda_bf16.h>

#define MAXN 50000
#define MAXE 800000
#define HDIM 96
#define HDIM2 192

// ---------------- scratch (device globals; no allocation allowed) ----------------
__device__ int   g_deg_in[MAXN];
__device__ int   g_deg_out[MAXN];
__device__ int   g_fill[MAXN];
__device__ int   g_rowptr[MAXN + 1];
__device__ int2  g_col2[MAXE];                 // {src, perm[src]} per edge (CSR by dst)
__device__ float g_norm_in[MAXN];
__device__ float g_norm_out[MAXN];
__device__ float g_Y[(size_t)MAXN * HDIM];     // x @ W1 (shared by both views)
__device__ float g_HB[(size_t)MAXN * HDIM2];   // split-K scratch, then layer-2 features
__device__ float g_P[(size_t)MAXN * HDIM2];    // layer-1 post-PReLU (view-major halves)
__device__ float g_wsum[HDIM];
__device__ float g_bmsum;

// packed f32x2 FMA: acc = a * b + acc
__device__ __forceinline__ void fma_f32x2(unsigned long long& acc,
                                          unsigned long long a,
                                          unsigned long long b) {
    asm("fma.rn.f32x2 %0, %1, %2, %0;" : "+l"(acc) : "l"(a), "l"(b));
}
__device__ __forceinline__ unsigned long long dupf(float f) {
    unsigned int u = __float_as_uint(f);
    return ((unsigned long long)u << 32) | u;
}

// ---------------- small setup kernels ----------------
__global__ void zero_kernel(int n) {
    int i = blockIdx.x * blockDim.x + threadIdx.x;
    if (i < n) { g_deg_in[i] = 0; g_deg_out[i] = 0; g_fill[i] = 0; }
}

__global__ void degree_kernel(const int* __restrict__ src, const int* __restrict__ dst, int e) {
    int i = blockIdx.x * blockDim.x + threadIdx.x;
    if (i < e) {
        atomicAdd(&g_deg_out[src[i]], 1);
        atomicAdd(&g_deg_in[dst[i]], 1);
    }
}

// Single-block exclusive scan of in-degrees -> rowptr; also norms + Wm row-sums.
__global__ void scan_kernel(int n, const float* __restrict__ Wm, const float* __restrict__ bm) {
    __shared__ int ssum[1024];
    int t = threadIdx.x;

    if (t < HDIM) {
        float s = 0.f;
        #pragma unroll 8
        for (int j = 0; j < HDIM; j++) s += Wm[t * HDIM + j];
        g_wsum[t] = s;
    }
    if (t == 0) {
        float s = 0.f;
        for (int j = 0; j < HDIM; j++) s += bm[j];
        g_bmsum = s;
    }

    int chunk = (n + 1023) / 1024;
    int beg = min(t * chunk, n);
    int end = min(beg + chunk, n);
    int s = 0;
    for (int i = beg; i < end; i++) s += g_deg_in[i];
    ssum[t] = s;
    __syncthreads();
    for (int off = 1; off < 1024; off <<= 1) {
        int v = (t >= off) ? ssum[t - off] : 0;
        __syncthreads();
        ssum[t] += v;
        __syncthreads();
    }
    int run = ssum[t] - s;
    for (int i = beg; i < end; i++) { g_rowptr[i] = run; run += g_deg_in[i]; }
    if (end == n) g_rowptr[n] = run;

    for (int i = beg; i < end; i++) {
        g_norm_in[i]  = rsqrtf((float)max(g_deg_in[i], 1));
        g_norm_out[i] = rsqrtf((float)max(g_deg_out[i], 1));
    }
}

__global__ void fill_kernel(const int* __restrict__ src, const int* __restrict__ dst,
                            const int* __restrict__ perm, int e) {
    int i = blockIdx.x * blockDim.x + threadIdx.x;
    if (i < e) {
        int d = dst[i];
        int s = src[i];
        int pos = g_rowptr[d] + atomicAdd(&g_fill[d], 1);
        g_col2[pos] = make_int2(s, perm[s]);
    }
}

// ---------------- pipelined f32x2 GEMM: C[m][0..95] = rowscale[m]*(A[m,kBeg:kEnd] @ B) --
// 128x96 tile, 256 threads, 8 rows x 6 cols per thread, row-pair-packed accumulators.
// Double-buffered smem, register-staged prefetch, conflict-free STS:
//  - A smem swizzled by m ^ ((kk&8)?8:0)  (store banks disjoint; read XOR folds into ty)
//  - B loaded via lane-consecutive scalar LDG.32, stored dup as lane-consecutive STS.64
__global__ __launch_bounds__(256, 2) void gemm96_kernel(
    const float* __restrict__ A, int lda,
    const float* __restrict__ B,
    float* __restrict__ C0, float* __restrict__ C1, int ldc,
    const float* __restrict__ rowscale,
    int M, int K, int splitK)
{
    __shared__ __align__(16) float As[2][16][132];           // [buf][kk][m-swizzled]
    __shared__ unsigned long long Bs2[2][16][96];            // [buf][kk][c] -> (b,b)

    int tid = threadIdx.x;
    int tx = tid & 15;          // cols tx + 16*c
    int ty = tid >> 4;          // rows ty*8 .. ty*8+7
    int row0 = blockIdx.x * 128;
    int y = blockIdx.y;

    const float* Ab; float* C; int kBeg, kEnd;
    const float* rs = rowscale;
    if (splitK > 0) {
        int kMid = min(splitK, K);
        Ab = A; C = y ? C1 : C0;
        kBeg = y ? kMid : 0; kEnd = y ? K : kMid;
    } else {
        Ab = A + y * HDIM; C = C0 + y * HDIM;
        kBeg = 0; kEnd = K;
    }

    // A load/store assignment
    int qa = tid & 3, ma = tid >> 2;           // float4 quad qa (k), rows ma / ma+64
    int rA0 = row0 + ma, rA1 = row0 + ma + 64;
    int mas = ma ^ ((qa & 2) ? 8 : 0);         // swizzled store row index
    // B load/store assignment: 6 lane-consecutive elements
    int bkk[6], bcc[6];
    #pragma unroll
    for (int i2 = 0; i2 < 6; i2++) {
        int idx = i2 * 256 + tid;              // 0..1535 over 16x96
        bkk[i2] = idx / 96;
        bcc[i2] = idx - bkk[i2] * 96;
    }

    float4 a0, a1;
    float bv[6];
    const float4 Z = make_float4(0.f, 0.f, 0.f, 0.f);

    auto ldg = [&](int k0) {
        int gk = k0 + 4 * qa;
        bool kok = (gk + 4 <= kEnd);
        a0 = (kok && rA0 < M) ? *(const float4*)&Ab[(size_t)rA0 * lda + gk] : Z;
        a1 = (kok && rA1 < M) ? *(const float4*)&Ab[(size_t)rA1 * lda + gk] : Z;
        #pragma unroll
        for (int i2 = 0; i2 < 6; i2++) {
            int g = k0 + bkk[i2];
            bv[i2] = (g < kEnd) ? B[(size_t)g * HDIM + bcc[i2]] : 0.f;
        }
    };
    auto sts = [&](int s) {
        As[s][4 * qa + 0][mas] = a0.x; As[s][4 * qa + 1][mas] = a0.y;
        As[s][4 * qa + 2][mas] = a0.z; As[s][4 * qa + 3][mas] = a0.w;
        As[s][4 * qa + 0][mas + 64] = a1.x; As[s][4 * qa + 1][mas + 64] = a1.y;
        As[s][4 * qa + 2][mas + 64] = a1.z; As[s][4 * qa + 3][mas + 64] = a1.w;
        #pragma unroll
        for (int i2 = 0; i2 < 6; i2++)
            Bs2[s][bkk[i2]][bcc[i2]] = dupf(bv[i2]);
    };

    unsigned long long acc[4][6];
    #pragma unroll
    for (int r = 0; r < 4; r++)
        #pragma unroll
        for (int c = 0; c < 6; c++) acc[r][c] = 0ull;

    int rbA = ty * 8;            // A read base, kk < 8
    int rbB = (ty ^ 1) * 8;      // A read base, kk >= 8 (swizzle)

    int nk = (kEnd - kBeg + 15) >> 4;
    ldg(kBeg);
    sts(0);
    for (int i = 0; i < nk; i++) {
        __syncthreads();
        if (i + 1 < nk) ldg(kBeg + (i + 1) * 16);
        int s = i & 1;
        #pragma unroll
        for (int kk = 0; kk < 16; kk++) {
            int rb = (kk & 8) ? rbB : rbA;
            ulonglong2 apl = *(const ulonglong2*)&As[s][kk][rb];
            ulonglong2 aph = *(const ulonglong2*)&As[s][kk][rb + 4];
            unsigned long long ap[4] = {apl.x, apl.y, aph.x, aph.y};
            unsigned long long bp[6];
            #pragma unroll
            for (int c = 0; c < 6; c++) bp[c] = Bs2[s][kk][tx + 16 * c];
            #pragma unroll
            for (int r = 0; r < 4; r++)
                #pragma unroll
                for (int c = 0; c < 6; c++)
                    fma_f32x2(acc[r][c], ap[r], bp[c]);
        }
        if (i + 1 < nk) sts((i + 1) & 1);
    }

    bool doScale = (rs != nullptr) && (splitK == 0);
    #pragma unroll
    for (int r = 0; r < 4; r++) {
        int m0 = row0 + ty * 8 + 2 * r;
        #pragma unroll
        for (int h = 0; h < 2; h++) {
            int m = m0 + h;
            if (m < M) {
                float sc = doScale ? rs[m] : 1.f;
                #pragma unroll
                for (int c = 0; c < 6; c++) {
                    unsigned int u = (unsigned int)(h ? (acc[r][c] >> 32)
                                                      : (acc[r][c] & 0xffffffffull));
                    C[(size_t)m * ldc + tx + 16 * c] = __uint_as_float(u) * sc;
                }
            }
        }
    }
}

// Y += split-K partial (float4 vectorized)
__global__ void add_kernel(float* __restrict__ dst, const float* __restrict__ srcp, int n4) {
    int i = blockIdx.x * blockDim.x + threadIdx.x;
    if (i < n4) {
        float4 a = ((const float4*)dst)[i];
        float4 b = ((const float4*)srcp)[i];
        a.x += b.x; a.y += b.y; a.z += b.z; a.w += b.w;
        ((float4*)dst)[i] = a;
    }
}

// ---------------- layer-1 aggregation: gathers Y directly (dual view, half-warp each) --
__global__ __launch_bounds__(256) void spmm1_kernel(
    const float* __restrict__ Y, float* __restrict__ Pout,
    const float* __restrict__ b, const float* __restrict__ a, int n)
{
    int gw = (blockIdx.x * blockDim.x + threadIdx.x) >> 5;
    int lane = threadIdx.x & 31;
    if (gw >= n) return;
    int half = lane >> 4;        // 0: view1 (Y[s]), 1: view2 (Y[perm[s]])
    int l = lane & 15;

    int beg = g_rowptr[gw], end = g_rowptr[gw + 1];
    float2 acc0 = {0.f, 0.f}, acc1 = {0.f, 0.f}, acc2 = {0.f, 0.f};

    int e = beg;
    for (; e + 1 < end; e += 2) {
        int2 sp0 = g_col2[e], sp1 = g_col2[e + 1];
        float ns0 = g_norm_out[sp0.x], ns1 = g_norm_out[sp1.x];
        int s0 = half ? sp0.y : sp0.x;
        int s1 = half ? sp1.y : sp1.x;
        const float2* h0 = (const float2*)(Y + (size_t)s0 * HDIM);
        const float2* h1 = (const float2*)(Y + (size_t)s1 * HDIM);
        float2 u0 = h0[l], u1 = h0[l + 16], u2 = h0[l + 32];
        float2 v0 = h1[l], v1 = h1[l + 16], v2 = h1[l + 32];
        acc0.x += ns0 * u0.x + ns1 * v0.x; acc0.y += ns0 * u0.y + ns1 * v0.y;
        acc1.x += ns0 * u1.x + ns1 * v1.x; acc1.y += ns0 * u1.y + ns1 * v1.y;
        acc2.x += ns0 * u2.x + ns1 * v2.x; acc2.y += ns0 * u2.y + ns1 * v2.y;
    }
    if (e < end) {
        int2 sp0 = g_col2[e];
        float ns0 = g_norm_out[sp0.x];
        int s0 = half ? sp0.y : sp0.x;
        const float2* h0 = (const float2*)(Y + (size_t)s0 * HDIM);
        float2 u0 = h0[l], u1 = h0[l + 16], u2 = h0[l + 32];
        acc0.x += ns0 * u0.x; acc0.y += ns0 * u0.y;
        acc1.x += ns0 * u1.x; acc1.y += ns0 * u1.y;
        acc2.x += ns0 * u2.x; acc2.y += ns0 * u2.y;
    }

    float ni = g_norm_in[gw];
    float2* po = (float2*)(Pout + (size_t)gw * HDIM2);

    #pragma unroll
    for (int j = 0; j < 3; j++) {
        int idx = l + 16 * j;
        int c0 = 2 * idx;
        float2 acc = (j == 0) ? acc0 : (j == 1) ? acc1 : acc2;
        float h0 = acc.x * ni + b[c0];
        float h1 = acc.y * ni + b[c0 + 1];
        float z0 = (h0 >= 0.f) ? h0 : a[c0] * h0;
        float z1 = (h1 >= 0.f) ? h1 : a[c0 + 1] * h1;
        po[half * 48 + idx] = make_float2(z0, z1);
    }
}

// ---------------- layer-2 aggregation + PReLU + fused projection row-sum ---------------
__global__ __launch_bounds__(256) void spmm2_kernel(
    const float* __restrict__ Hin,
    const float* __restrict__ b, const float* __restrict__ a,
    float* __restrict__ out, int n)
{
    int gw = (blockIdx.x * blockDim.x + threadIdx.x) >> 5;
    int lane = threadIdx.x & 31;
    if (gw >= n) return;

    int beg = g_rowptr[gw], end = g_rowptr[gw + 1];
    float2 acc0 = {0.f, 0.f}, acc1 = {0.f, 0.f}, acc2 = {0.f, 0.f};

    int e = beg;
    for (; e + 1 < end; e += 2) {
        int s0 = g_col2[e].x, s1 = g_col2[e + 1].x;
        const float2* h0 = (const float2*)(Hin + (size_t)s0 * HDIM2);
        const float2* h1 = (const float2*)(Hin + (size_t)s1 * HDIM2);
        float2 u0 = h0[lane], u1 = h0[lane + 32], u2 = h0[lane + 64];
        float2 v0 = h1[lane], v1 = h1[lane + 32], v2 = h1[lane + 64];
        acc0.x += u0.x + v0.x; acc0.y += u0.y + v0.y;
        acc1.x += u1.x + v1.x; acc1.y += u1.y + v1.y;
        acc2.x += u2.x + v2.x; acc2.y += u2.y + v2.y;
    }
    if (e < end) {
        int s0 = g_col2[e].x;
        const float2* h0 = (const float2*)(Hin + (size_t)s0 * HDIM2);
        float2 u0 = h0[lane], u1 = h0[lane + 32], u2 = h0[lane + 64];
        acc0.x += u0.x; acc0.y += u0.y;
        acc1.x += u1.x; acc1.y += u1.y;
        acc2.x += u2.x; acc2.y += u2.y;
    }

    float ni = g_norm_in[gw];
    float s1 = 0.f, s2 = 0.f;

    #pragma unroll
    for (int j = 0; j < 3; j++) {
        int idx = lane + 32 * j;
        float2 acc = (j == 0) ? acc0 : (j == 1) ? acc1 : acc2;
        int v = idx >= 48;
        int c0 = 2 * idx - 96 * v;
        float h0 = acc.x * ni + b[c0];
        float h1 = acc.y * ni + b[c0 + 1];
        float z0 = (h0 >= 0.f) ? h0 : a[c0] * h0;
        float z1 = (h1 >= 0.f) ? h1 : a[c0 + 1] * h1;
        float contrib = z0 * g_wsum[c0] + z1 * g_wsum[c0 + 1];
        if (v) s2 += contrib; else s1 += contrib;
    }

    #pragma unroll
    for (int off = 16; off > 0; off >>= 1) {
        s1 += __shfl_xor_sync(0xffffffff, s1, off);
        s2 += __shfl_xor_sync(0xffffffff, s2, off);
    }
    if (lane == 0) {
        out[gw]     = s1 + g_bmsum;
        out[n + gw] = s2 + g_bmsum;
    }
}

// ---------------- launch ----------------
extern "C" void kernel_launch(void* const* d_in, const int* in_sizes, int n_in,
                              void* d_out, int out_size) {
    const float* x   = (const float*)d_in[0];
    const int*   src = (const int*)  d_in[1];
    const int*   dst = (const int*)  d_in[2];
    const int*   perm= (const int*)  d_in[3];
    const float* W1  = (const float*)d_in[4];
    const float* b1  = (const float*)d_in[5];
    const float* a1  = (const float*)d_in[6];
    const float* W2  = (const float*)d_in[7];
    const float* b2  = (const float*)d_in[8];
    const float* a2  = (const float*)d_in[9];
    const float* Wm  = (const float*)d_in[10];
    const float* bm  = (const float*)d_in[11];
    float* out = (float*)d_out;

    int E = in_sizes[1];
    int n = in_sizes[3];
    int F = in_sizes[0] / n;

    float *pY, *pHB, *pP, *pNormOut;
    cudaGetSymbolAddress((void**)&pY, g_Y);
    cudaGetSymbolAddress((void**)&pHB, g_HB);
    cudaGetSymbolAddress((void**)&pP, g_P);
    cudaGetSymbolAddress((void**)&pNormOut, g_norm_out);

    int nTiles = (n + 127) / 128;

    zero_kernel<<<(n + 255) / 256, 256>>>(n);
    degree_kernel<<<(E + 255) / 256, 256>>>(src, dst, E);
    scan_kernel<<<1, 1024>>>(n, Wm, bm);
    // Y = X @ W1, split-K=2 (y=0: K[0,256) -> Y; y=1: K[256,F) -> HB scratch)
    gemm96_kernel<<<dim3(nTiles, 2), 256>>>(x, F, W1, pY, pHB, HDIM, nullptr, n, F, 256);
    add_kernel<<<(n * HDIM / 4 + 255) / 256, 256>>>(pY, pHB, n * HDIM / 4);
    fill_kernel<<<(E + 255) / 256, 256>>>(src, dst, perm, E);
    // layer-1 aggregation (dual view, direct gather from Y) + PReLU
    spmm1_kernel<<<(n + 7) / 8, 256>>>(pY, pP, b1, a1, n);
    // layer-2 GEMMs, both views in one launch, norm_out fused in epilogue
    gemm96_kernel<<<dim3(nTiles, 2), 256>>>(pP, HDIM2, W2, pHB, nullptr, HDIM2, pNormOut, n, HDIM, 0);
    // layer-2 aggregation + PReLU + fused projection row-sum
    spmm2_kernel<<<(n + 7) / 8, 256>>>(pHB, b2, a2, out, n);
}

// round 8
// speedup vs baseline: 1.3908x; 1.3908x over previous
#include <cuda_runtime.h>
#include <cstdint>

#define MAXN 50000
#define MAXE 800000
#define HDIM 96
#define HDIM2 192

// ---------------- scratch (device globals; no allocation allowed) ----------------
__device__ int   g_deg_in[MAXN];
__device__ int   g_deg_out[MAXN];
__device__ int   g_fill[MAXN];
__device__ int   g_rowptr[MAXN + 1];
__device__ int2  g_col2[MAXE];                 // {src, perm[src]} per edge (CSR by dst)
__device__ float g_norm_in[MAXN];
__device__ float g_norm_out[MAXN];
__device__ float g_Y[(size_t)MAXN * HDIM];     // x @ W1 (shared by both views)
__device__ float g_HB[(size_t)MAXN * HDIM2];   // layer-2 pre-aggregation features
__device__ float g_P[(size_t)MAXN * HDIM2];    // layer-1 post-PReLU (view-major halves)
__device__ float g_wsum[HDIM];
__device__ float g_bmsum;

// ---------------- tf32 helpers ----------------
__device__ __forceinline__ uint32_t f2tf32(float x) {
    uint32_t u;
    asm("cvt.rna.tf32.f32 %0, %1;" : "=r"(u) : "f"(x));
    return u;
}
__device__ __forceinline__ void mma_tf32(float* c, const uint32_t* a,
                                         uint32_t b0, uint32_t b1) {
    asm volatile(
        "mma.sync.aligned.m16n8k8.row.col.f32.tf32.tf32.f32 "
        "{%0,%1,%2,%3},{%4,%5,%6,%7},{%8,%9},{%0,%1,%2,%3};"
        : "+f"(c[0]), "+f"(c[1]), "+f"(c[2]), "+f"(c[3])
        : "r"(a[0]), "r"(a[1]), "r"(a[2]), "r"(a[3]), "r"(b0), "r"(b1));
}

// ---------------- small setup kernels ----------------
__global__ void zero_kernel(int n) {
    int i = blockIdx.x * blockDim.x + threadIdx.x;
    if (i < n) { g_deg_in[i] = 0; g_deg_out[i] = 0; g_fill[i] = 0; }
}

__global__ void degree_kernel(const int* __restrict__ src, const int* __restrict__ dst, int e) {
    int i = blockIdx.x * blockDim.x + threadIdx.x;
    if (i < e) {
        atomicAdd(&g_deg_out[src[i]], 1);
        atomicAdd(&g_deg_in[dst[i]], 1);
    }
}

__global__ void scan_kernel(int n, const float* __restrict__ Wm, const float* __restrict__ bm) {
    __shared__ int ssum[1024];
    int t = threadIdx.x;

    if (t < HDIM) {
        float s = 0.f;
        #pragma unroll 8
        for (int j = 0; j < HDIM; j++) s += Wm[t * HDIM + j];
        g_wsum[t] = s;
    }
    if (t == 0) {
        float s = 0.f;
        for (int j = 0; j < HDIM; j++) s += bm[j];
        g_bmsum = s;
    }

    int chunk = (n + 1023) / 1024;
    int beg = min(t * chunk, n);
    int end = min(beg + chunk, n);
    int s = 0;
    for (int i = beg; i < end; i++) s += g_deg_in[i];
    ssum[t] = s;
    __syncthreads();
    for (int off = 1; off < 1024; off <<= 1) {
        int v = (t >= off) ? ssum[t - off] : 0;
        __syncthreads();
        ssum[t] += v;
        __syncthreads();
    }
    int run = ssum[t] - s;
    for (int i = beg; i < end; i++) { g_rowptr[i] = run; run += g_deg_in[i]; }
    if (end == n) g_rowptr[n] = run;

    for (int i = beg; i < end; i++) {
        g_norm_in[i]  = rsqrtf((float)max(g_deg_in[i], 1));
        g_norm_out[i] = rsqrtf((float)max(g_deg_out[i], 1));
    }
}

__global__ void fill_kernel(const int* __restrict__ src, const int* __restrict__ dst,
                            const int* __restrict__ perm, int e) {
    int i = blockIdx.x * blockDim.x + threadIdx.x;
    if (i < e) {
        int d = dst[i];
        int s = src[i];
        int pos = g_rowptr[d] + atomicAdd(&g_fill[d], 1);
        g_col2[pos] = make_int2(s, perm[s]);
    }
}

// ---------------- tf32 mma.sync GEMM: C[m][0..95] = rowscale[m]*(A[m,:K] @ B[K,96]) ----
// CTA tile 128x96, 8 warps (4 m-rows x 2 n-cols), warp tile 32x48 (2x6 m16n8 atoms),
// K-chunks of 32 (4 ksteps of k8), double-buffered smem, tf32 conversion at STS.
// smem: A [128][36] floats (stride 36 -> conflict-free frag reads), B [96][35] (n-major).
#define ASTR 36
#define BSTR 35
#define BUFF 7968   // floats per buffer: 128*36 + 96*35
__global__ __launch_bounds__(256) void gemm_mma_kernel(
    const float* __restrict__ A, int lda, int viewA,
    const float* __restrict__ B,
    float* __restrict__ C, int ldc, int viewC,
    const float* __restrict__ rowscale,
    int M, int K)
{
    extern __shared__ float smf[];

    int tid = threadIdx.x;
    int wid = tid >> 5, lane = tid & 31;
    int g = lane >> 2, t = lane & 3;
    int wm = (wid & 3) * 32;        // warp m offset in tile
    int wn = (wid >> 2) * 48;       // warp n offset
    int row0 = blockIdx.x * 128;
    A += (size_t)blockIdx.y * viewA;
    C += (size_t)blockIdx.y * viewC;

    float acc[2][6][4];
    #pragma unroll
    for (int ma = 0; ma < 2; ma++)
        #pragma unroll
        for (int na = 0; na < 6; na++)
            #pragma unroll
            for (int c = 0; c < 4; c++) acc[ma][na][c] = 0.f;

    // staging registers
    float4 av[4];
    float bv[12];
    const float4 Z4 = make_float4(0.f, 0.f, 0.f, 0.f);

    auto ldg = [&](int k0) {
        bool fullk = (k0 + 32 <= K);
        #pragma unroll
        for (int j = 0; j < 4; j++) {
            int idx = tid + j * 256;          // 0..1023
            int r = idx >> 3, q = idx & 7;
            int gr = row0 + r;
            float4 v = Z4;
            if (gr < M) {
                const float* ap = A + (size_t)gr * lda + k0 + 4 * q;
                if (fullk || k0 + 4 * q + 4 <= K) v = *(const float4*)ap;
                else {
                    int kb = k0 + 4 * q;
                    if (kb + 0 < K) v.x = ap[0];
                    if (kb + 1 < K) v.y = ap[1];
                    if (kb + 2 < K) v.z = ap[2];
                }
            }
            av[j] = v;
        }
        #pragma unroll
        for (int j = 0; j < 12; j++) {
            int idx = tid + j * 256;          // 0..3071 over [kk][c]
            int kk = idx / 96, c = idx - kk * 96;
            bv[j] = (k0 + kk < K) ? B[(size_t)(k0 + kk) * HDIM + c] : 0.f;
        }
    };
    auto sts = [&](int s) {
        float* Asm = smf + s * BUFF;
        float* Bsm = smf + s * BUFF + 128 * ASTR;
        #pragma unroll
        for (int j = 0; j < 4; j++) {
            int idx = tid + j * 256;
            int r = idx >> 3, q = idx & 7;
            float4 w;
            w.x = __uint_as_float(f2tf32(av[j].x));
            w.y = __uint_as_float(f2tf32(av[j].y));
            w.z = __uint_as_float(f2tf32(av[j].z));
            w.w = __uint_as_float(f2tf32(av[j].w));
            *(float4*)&Asm[r * ASTR + 4 * q] = w;
        }
        #pragma unroll
        for (int j = 0; j < 12; j++) {
            int idx = tid + j * 256;
            int kk = idx / 96, c = idx - kk * 96;
            Bsm[c * BSTR + kk] = __uint_as_float(f2tf32(bv[j]));
        }
    };

    int nchunks = (K + 31) >> 5;
    ldg(0);
    sts(0);
    for (int i = 0; i < nchunks; i++) {
        __syncthreads();
        if (i + 1 < nchunks) ldg((i + 1) << 5);
        int s = i & 1;
        const float* Asm = smf + s * BUFF;
        const float* Bsm = smf + s * BUFF + 128 * ASTR;
        #pragma unroll
        for (int ks = 0; ks < 4; ks++) {
            int k = ks * 8;
            uint32_t ar[2][4];
            #pragma unroll
            for (int ma = 0; ma < 2; ma++) {
                int rb = (wm + 16 * ma + g) * ASTR + k + t;
                ar[ma][0] = __float_as_uint(Asm[rb]);
                ar[ma][1] = __float_as_uint(Asm[rb + 8 * ASTR]);
                ar[ma][2] = __float_as_uint(Asm[rb + 4]);
                ar[ma][3] = __float_as_uint(Asm[rb + 8 * ASTR + 4]);
            }
            #pragma unroll
            for (int na = 0; na < 6; na++) {
                int bb = (wn + 8 * na + g) * BSTR + k + t;
                uint32_t b0 = __float_as_uint(Bsm[bb]);
                uint32_t b1 = __float_as_uint(Bsm[bb + 4]);
                mma_tf32(acc[0][na], ar[0], b0, b1);
                mma_tf32(acc[1][na], ar[1], b0, b1);
            }
        }
        if (i + 1 < nchunks) sts((i + 1) & 1);
    }

    // epilogue: c0/c1 -> (row g, cols 2t,2t+1); c2/c3 -> row g+8
    #pragma unroll
    for (int ma = 0; ma < 2; ma++) {
        int r0 = row0 + wm + 16 * ma + g;
        int r1 = r0 + 8;
        float s0 = 1.f, s1 = 1.f;
        if (rowscale) {
            if (r0 < M) s0 = rowscale[r0];
            if (r1 < M) s1 = rowscale[r1];
        }
        #pragma unroll
        for (int na = 0; na < 6; na++) {
            int col = wn + 8 * na + 2 * t;
            if (r0 < M) {
                float2 v = make_float2(acc[ma][na][0] * s0, acc[ma][na][1] * s0);
                *(float2*)&C[(size_t)r0 * ldc + col] = v;
            }
            if (r1 < M) {
                float2 v = make_float2(acc[ma][na][2] * s1, acc[ma][na][3] * s1);
                *(float2*)&C[(size_t)r1 * ldc + col] = v;
            }
        }
    }
}

// ---------------- layer-1 aggregation: gathers Y directly (dual view, half-warp each) --
__global__ __launch_bounds__(256) void spmm1_kernel(
    const float* __restrict__ Y, float* __restrict__ Pout,
    const float* __restrict__ b, const float* __restrict__ a, int n)
{
    int gw = (blockIdx.x * blockDim.x + threadIdx.x) >> 5;
    int lane = threadIdx.x & 31;
    if (gw >= n) return;
    int half = lane >> 4;        // 0: view1 (Y[s]), 1: view2 (Y[perm[s]])
    int l = lane & 15;

    int beg = g_rowptr[gw], end = g_rowptr[gw + 1];
    float2 acc0 = {0.f, 0.f}, acc1 = {0.f, 0.f}, acc2 = {0.f, 0.f};

    int e = beg;
    for (; e + 1 < end; e += 2) {
        int2 sp0 = g_col2[e], sp1 = g_col2[e + 1];
        float ns0 = g_norm_out[sp0.x], ns1 = g_norm_out[sp1.x];
        int s0 = half ? sp0.y : sp0.x;
        int s1 = half ? sp1.y : sp1.x;
        const float2* h0 = (const float2*)(Y + (size_t)s0 * HDIM);
        const float2* h1 = (const float2*)(Y + (size_t)s1 * HDIM);
        float2 u0 = h0[l], u1 = h0[l + 16], u2 = h0[l + 32];
        float2 v0 = h1[l], v1 = h1[l + 16], v2 = h1[l + 32];
        acc0.x += ns0 * u0.x + ns1 * v0.x; acc0.y += ns0 * u0.y + ns1 * v0.y;
        acc1.x += ns0 * u1.x + ns1 * v1.x; acc1.y += ns0 * u1.y + ns1 * v1.y;
        acc2.x += ns0 * u2.x + ns1 * v2.x; acc2.y += ns0 * u2.y + ns1 * v2.y;
    }
    if (e < end) {
        int2 sp0 = g_col2[e];
        float ns0 = g_norm_out[sp0.x];
        int s0 = half ? sp0.y : sp0.x;
        const float2* h0 = (const float2*)(Y + (size_t)s0 * HDIM);
        float2 u0 = h0[l], u1 = h0[l + 16], u2 = h0[l + 32];
        acc0.x += ns0 * u0.x; acc0.y += ns0 * u0.y;
        acc1.x += ns0 * u1.x; acc1.y += ns0 * u1.y;
        acc2.x += ns0 * u2.x; acc2.y += ns0 * u2.y;
    }

    float ni = g_norm_in[gw];
    float2* po = (float2*)(Pout + (size_t)gw * HDIM2);

    #pragma unroll
    for (int j = 0; j < 3; j++) {
        int idx = l + 16 * j;
        int c0 = 2 * idx;
        float2 acc = (j == 0) ? acc0 : (j == 1) ? acc1 : acc2;
        float h0 = acc.x * ni + b[c0];
        float h1 = acc.y * ni + b[c0 + 1];
        float z0 = (h0 >= 0.f) ? h0 : a[c0] * h0;
        float z1 = (h1 >= 0.f) ? h1 : a[c0 + 1] * h1;
        po[half * 48 + idx] = make_float2(z0, z1);
    }
}

// ---------------- layer-2 aggregation + PReLU + fused projection row-sum ---------------
__global__ __launch_bounds__(256) void spmm2_kernel(
    const float* __restrict__ Hin,
    const float* __restrict__ b, const float* __restrict__ a,
    float* __restrict__ out, int n)
{
    int gw = (blockIdx.x * blockDim.x + threadIdx.x) >> 5;
    int lane = threadIdx.x & 31;
    if (gw >= n) return;

    int beg = g_rowptr[gw], end = g_rowptr[gw + 1];
    float2 acc0 = {0.f, 0.f}, acc1 = {0.f, 0.f}, acc2 = {0.f, 0.f};

    int e = beg;
    for (; e + 1 < end; e += 2) {
        int s0 = g_col2[e].x, s1 = g_col2[e + 1].x;
        const float2* h0 = (const float2*)(Hin + (size_t)s0 * HDIM2);
        const float2* h1 = (const float2*)(Hin + (size_t)s1 * HDIM2);
        float2 u0 = h0[lane], u1 = h0[lane + 32], u2 = h0[lane + 64];
        float2 v0 = h1[lane], v1 = h1[lane + 32], v2 = h1[lane + 64];
        acc0.x += u0.x + v0.x; acc0.y += u0.y + v0.y;
        acc1.x += u1.x + v1.x; acc1.y += u1.y + v1.y;
        acc2.x += u2.x + v2.x; acc2.y += u2.y + v2.y;
    }
    if (e < end) {
        int s0 = g_col2[e].x;
        const float2* h0 = (const float2*)(Hin + (size_t)s0 * HDIM2);
        float2 u0 = h0[lane], u1 = h0[lane + 32], u2 = h0[lane + 64];
        acc0.x += u0.x; acc0.y += u0.y;
        acc1.x += u1.x; acc1.y += u1.y;
        acc2.x += u2.x; acc2.y += u2.y;
    }

    float ni = g_norm_in[gw];
    float s1 = 0.f, s2 = 0.f;

    #pragma unroll
    for (int j = 0; j < 3; j++) {
        int idx = lane + 32 * j;
        float2 acc = (j == 0) ? acc0 : (j == 1) ? acc1 : acc2;
        int v = idx >= 48;
        int c0 = 2 * idx - 96 * v;
        float h0 = acc.x * ni + b[c0];
        float h1 = acc.y * ni + b[c0 + 1];
        float z0 = (h0 >= 0.f) ? h0 : a[c0] * h0;
        float z1 = (h1 >= 0.f) ? h1 : a[c0 + 1] * h1;
        float contrib = z0 * g_wsum[c0] + z1 * g_wsum[c0 + 1];
        if (v) s2 += contrib; else s1 += contrib;
    }

    #pragma unroll
    for (int off = 16; off > 0; off >>= 1) {
        s1 += __shfl_xor_sync(0xffffffff, s1, off);
        s2 += __shfl_xor_sync(0xffffffff, s2, off);
    }
    if (lane == 0) {
        out[gw]     = s1 + g_bmsum;
        out[n + gw] = s2 + g_bmsum;
    }
}

// ---------------- launch ----------------
extern "C" void kernel_launch(void* const* d_in, const int* in_sizes, int n_in,
                              void* d_out, int out_size) {
    const float* x   = (const float*)d_in[0];
    const int*   src = (const int*)  d_in[1];
    const int*   dst = (const int*)  d_in[2];
    const int*   perm= (const int*)  d_in[3];
    const float* W1  = (const float*)d_in[4];
    const float* b1  = (const float*)d_in[5];
    const float* a1  = (const float*)d_in[6];
    const float* W2  = (const float*)d_in[7];
    const float* b2  = (const float*)d_in[8];
    const float* a2  = (const float*)d_in[9];
    const float* Wm  = (const float*)d_in[10];
    const float* bm  = (const float*)d_in[11];
    float* out = (float*)d_out;

    int E = in_sizes[1];
    int n = in_sizes[3];
    int F = in_sizes[0] / n;

    float *pY, *pHB, *pP, *pNormOut;
    cudaGetSymbolAddress((void**)&pY, g_Y);
    cudaGetSymbolAddress((void**)&pHB, g_HB);
    cudaGetSymbolAddress((void**)&pP, g_P);
    cudaGetSymbolAddress((void**)&pNormOut, g_norm_out);

    const int SMEM_BYTES = 2 * BUFF * 4;   // 63744
    static int attrSet = 0;
    if (!attrSet) {
        cudaFuncSetAttribute(gemm_mma_kernel,
                             cudaFuncAttributeMaxDynamicSharedMemorySize, SMEM_BYTES);
        attrSet = 1;
    }

    int nTiles = (n + 127) / 128;

    zero_kernel<<<(n + 255) / 256, 256>>>(n);
    degree_kernel<<<(E + 255) / 256, 256>>>(src, dst, E);
    scan_kernel<<<1, 1024>>>(n, Wm, bm);
    // Y = X @ W1 (tf32 mma.sync tensor cores)
    gemm_mma_kernel<<<dim3(nTiles, 1), 256, SMEM_BYTES>>>(
        x, F, 0, W1, pY, HDIM, 0, nullptr, n, F);
    fill_kernel<<<(E + 255) / 256, 256>>>(src, dst, perm, E);
    // layer-1 aggregation (dual view, direct gather from Y) + PReLU
    spmm1_kernel<<<(n + 7) / 8, 256>>>(pY, pP, b1, a1, n);
    // layer-2 GEMMs, both views in one launch (grid.y), norm_out fused in epilogue
    gemm_mma_kernel<<<dim3(nTiles, 2), 256, SMEM_BYTES>>>(
        pP, HDIM2, HDIM, W2, pHB, HDIM2, HDIM, pNormOut, n, HDIM);
    // layer-2 aggregation + PReLU + fused projection row-sum
    spmm2_kernel<<<(n + 7) / 8, 256>>>(pHB, b2, a2, out, n);
}